// round 5
// baseline (speedup 1.0000x reference)
#include <cuda_runtime.h>
#include <cstdint>

#define S_STEPS 19648   // B*N = 64*307 sequential LSTM steps
#define NCH 12          // T_IN: independent LSTM chains
#define HID 128
#define CLS 8           // CTAs per chain (cluster size)
#define NROWS_TOTAL (S_STEPS * NCH)

// h history for deferred output projection: 19648*12*128 floats = ~115 MB
__device__ float g_hhist[(size_t)S_STEPS * NCH * HID];

// ---------------- PTX helpers ----------------
__device__ __forceinline__ uint32_t smem_u32(const void* p) {
    uint32_t a;
    asm("{ .reg .u64 t; cvta.to.shared.u64 t, %1; cvt.u32.u64 %0, t; }"
        : "=r"(a) : "l"(p));
    return a;
}
__device__ __forceinline__ uint32_t my_cluster_rank() {
    uint32_t r; asm("mov.u32 %0, %%cluster_ctarank;" : "=r"(r)); return r;
}
__device__ __forceinline__ uint32_t mapa_u32(uint32_t laddr, uint32_t rk) {
    uint32_t r;
    asm("mapa.shared::cluster.u32 %0, %1, %2;" : "=r"(r) : "r"(laddr), "r"(rk));
    return r;
}
// 8-byte remote shared store with mbarrier transaction tracking.
__device__ __forceinline__ void st_async_b64(uint32_t raddr, unsigned long long v,
                                             uint32_t rmbar) {
    asm volatile(
        "st.async.shared::cluster.mbarrier::complete_tx::bytes.b64 [%0], %1, [%2];"
        :: "r"(raddr), "l"(v), "r"(rmbar) : "memory");
}
#define MBAR_INIT(a, n) \
    asm volatile("mbarrier.init.shared.b64 [%0], %1;" :: "r"(a), "r"((uint32_t)(n)) : "memory")
#define MBAR_EXPECT_TX(a, n) \
    asm volatile("mbarrier.arrive.expect_tx.shared.b64 _, [%0], %1;" :: "r"(a), "r"((uint32_t)(n)) : "memory")
#define MBAR_WAIT(a, par) do {                                              \
    asm volatile(                                                           \
        "{\n\t.reg .pred P1;\n\t"                                           \
        "WL_%=:\n\t"                                                        \
        "mbarrier.try_wait.parity.acquire.cta.shared::cta.b64 P1, [%0], %1, 0x989680;\n\t" \
        "@P1 bra.uni WD_%=;\n\t"                                            \
        "bra.uni WL_%=;\n\t"                                                \
        "WD_%=:\n\t}"                                                       \
        :: "r"(a), "r"((uint32_t)(par)) : "memory");                        \
} while (0)

__device__ __forceinline__ unsigned long long fma2(unsigned long long a,
                                                   unsigned long long b,
                                                   unsigned long long c) {
    unsigned long long d;
    asm("fma.rn.f32x2 %0, %1, %2, %3;" : "=l"(d) : "l"(a), "l"(b), "l"(c));
    return d;
}
__device__ __forceinline__ float unpack_sum(unsigned long long a) {
    uint32_t lo, hi;
    asm("mov.b64 {%0, %1}, %2;" : "=r"(lo), "=r"(hi) : "l"(a));
    return __uint_as_float(lo) + __uint_as_float(hi);
}
__device__ __forceinline__ unsigned long long pack2(float lo, float hi) {
    unsigned long long d;
    asm("mov.b64 %0, {%1, %2};" : "=l"(d) : "f"(lo), "f"(hi));
    return d;
}
__device__ __forceinline__ float tanh_fast(float x) {
    float y; asm("tanh.approx.f32 %0, %1;" : "=f"(y) : "f"(x)); return y;
}
__device__ __forceinline__ float sigmoid_fast(float x) {
    return fmaf(0.5f, tanh_fast(0.5f * x), 0.5f);
}
#define CLUSTER_SYNC() do { \
    asm volatile("barrier.cluster.arrive.aligned;" ::: "memory"); \
    asm volatile("barrier.cluster.wait.aligned;"   ::: "memory"); } while (0)

// ---------------- LSTM kernel ----------------
// 96 CTAs = 12 chains x 8-CTA clusters. CTA rank r owns hidden units
// [16r, 16r+16) = 64 gate rows. Lane layout within warp w:
//   l = 8*colblk + 2*g + uin   (colblk 0..3, gate g 0..3, uin 0..1)
//   unit  u = 16r + 2w + uin,  row = g*128 + u,  cols [32*colblk, 32*colblk+32)
// Gates computed REDUNDANTLY on all lanes (c replicated per lane) so that
// lanes 0..7 each publish ONE packed b64 (both units of the warp) to rank=lane:
// per-thread fan-out 1, 512 messages/cluster-step, 512B expect_tx per CTA.
__global__ void __launch_bounds__(256, 1) __cluster_dims__(CLS, 1, 1)
lstm_kernel(const float* __restrict__ x,
            const float* __restrict__ W_ih,
            const float* __restrict__ W_hh,
            const float* __restrict__ b_ih,
            const float* __restrict__ b_hh)
{
    __shared__ __align__(16) float h_sh[2][HID];   // double-buffered hidden state
    __shared__ __align__(8)  unsigned long long mbar[2];

    const int tid  = threadIdx.x;
    const int w    = tid >> 5;
    const int l    = tid & 31;
    const uint32_t rank = my_cluster_rank();
    const int chain = blockIdx.x / CLS;

    const int uin  = l & 1;                 // unit within warp's pair
    const int g    = (l >> 1) & 3;          // gate 0..3 (i,f,g,o)
    const int cb   = l >> 3;                // column block 0..3 (32 cols each)
    const int ug   = 16 * (int)rank + 2 * w + uin;  // global hidden unit
    const int row  = g * 128 + ug;          // row in W (4H x H)

    // Register-resident W_hh row chunk: 32 floats = 8 ull2 (16 regs)
    const ulonglong2* wrow =
        reinterpret_cast<const ulonglong2*>(W_hh + (size_t)row * HID + 32 * cb);
    ulonglong2 wv[8];
#pragma unroll
    for (int j = 0; j < 8; j++) wv[j] = wrow[j];

    const float wx0 = W_ih[row * 3 + 0];
    const float wx1 = W_ih[row * 3 + 1];
    const float wx2 = W_ih[row * 3 + 2];
    const float bsum = b_ih[row] + b_hh[row];

    if (tid < HID) h_sh[0][tid] = 0.f;

    const uint32_t mb_l0 = smem_u32(&mbar[0]);
    const uint32_t mb_l1 = smem_u32(&mbar[1]);
    if (tid == 0) {
        MBAR_INIT(mb_l0, 1);
        MBAR_INIT(mb_l1, 1);
        MBAR_EXPECT_TX(mb_l1, 512);   // step 0 fills buffer 1 (8 ranks x 16 x 4B)
    }
    __syncthreads();   // local h_sh[0] zeros + mbar init done
    CLUSTER_SYNC();    // mbar init visible cluster-wide before any st.async

    // Per-lane send target: lane l (<8) sends the warp's packed unit pair
    // (units 16*rank + 2w, +1) to rank l. One mapa per thread at init; buffer-1
    // and mbar addresses derived by constant local-address deltas.
    const uint32_t la_pair = smem_u32(&h_sh[0][16 * (int)rank + 2 * w]); // warp-uniform
    const uint32_t mybase  = mapa_u32(la_pair, (uint32_t)(l & 7));
    const uint32_t d_h1    = (uint32_t)(HID * sizeof(float));  // h_sh[1] - h_sh[0]
    const uint32_t d_mb0   = mb_l0 - la_pair;
    const uint32_t d_mb1   = mb_l1 - la_pair;

    float c = 0.f;        // cell state (replicated across all lanes of the warp)
    int ph0 = 0, ph1 = 0; // mbarrier phase parities

    // x layout: (B,N,F,T) -> element (s,f,t) at x[s*36 + f*12 + t]
    float x0 = x[chain], x1 = x[12 + chain], x2 = x[24 + chain];

#define LSTM_STEP(s, P)                                                        \
    {                                                                          \
        const int b = 1 - (P);                                                 \
        if (tid == 0 && (s) > 0 && (s) < S_STEPS - 1)                          \
            MBAR_EXPECT_TX((b) ? mb_l1 : mb_l0, 512);                          \
        /* prefetch next x (L2-resident, hidden under the wait) */             \
        float nx0 = 0.f, nx1 = 0.f, nx2 = 0.f;                                 \
        if ((s) + 1 < S_STEPS) {                                               \
            const float* xp = x + (size_t)((s) + 1) * 36 + chain;              \
            nx0 = __ldg(xp); nx1 = __ldg(xp + 12); nx2 = __ldg(xp + 24);       \
        }                                                                      \
        /* wait for all 128 h of step s (st.async from all 8 ranks) */         \
        if ((s) > 0) {                                                         \
            if (P) { MBAR_WAIT(mb_l1, ph1); ph1 ^= 1; }                        \
            else   { MBAR_WAIT(mb_l0, ph0); ph0 ^= 1; }                        \
        }                                                                      \
        /* 32-col chunk of one row: 16 fma2, 4 accumulator chains */           \
        const ulonglong2* h4 =                                                 \
            reinterpret_cast<const ulonglong2*>(&h_sh[P][32 * cb]);            \
        unsigned long long a0 = 0ull, a1 = 0ull, a2 = 0ull, a3 = 0ull;         \
        _Pragma("unroll")                                                      \
        for (int j = 0; j < 8; j += 2) {                                       \
            ulonglong2 hva = h4[j];                                            \
            a0 = fma2(wv[j].x, hva.x, a0);                                     \
            a1 = fma2(wv[j].y, hva.y, a1);                                     \
            ulonglong2 hvb = h4[j + 1];                                        \
            a2 = fma2(wv[j + 1].x, hvb.x, a2);                                 \
            a3 = fma2(wv[j + 1].y, hvb.y, a3);                                 \
        }                                                                      \
        float zs = (unpack_sum(a0) + unpack_sum(a1))                           \
                 + (unpack_sum(a2) + unpack_sum(a3));                          \
        const unsigned fm = 0xffffffffu;                                       \
        zs += __shfl_xor_sync(fm, zs, 8);                                      \
        zs += __shfl_xor_sync(fm, zs, 16);                                     \
        float z = zs + bsum + wx0 * x0 + wx1 * x1 + wx2 * x2;                  \
        /* gather 4 gates of unit (l&1): lanes uin+2g, same for all lanes */   \
        float zi = __shfl_sync(fm, z, uin);                                    \
        float zf = __shfl_sync(fm, z, uin + 2);                                \
        float zg = __shfl_sync(fm, z, uin + 4);                                \
        float zo = __shfl_sync(fm, z, uin + 6);                                \
        /* gates on ALL lanes (warp-level MUFUs are free; c replicated) */     \
        float si = sigmoid_fast(zi);                                           \
        float sf = sigmoid_fast(zf);                                           \
        float so = sigmoid_fast(zo);                                           \
        c = sf * c + si * tanh_fast(zg);                                       \
        float hv = so * tanh_fast(c);                                          \
        /* pack warp's unit pair: (h[2w], h[2w+1]) */                          \
        float ho = __shfl_xor_sync(fm, hv, 1);                                 \
        unsigned long long hp = uin ? pack2(ho, hv) : pack2(hv, ho);           \
        if ((s) + 1 < S_STEPS && l < 8)                                        \
            st_async_b64(mybase + ((b) ? d_h1 : 0u), hp,                       \
                         mybase + ((b) ? d_mb1 : d_mb0));                      \
        if (l < 2)                                                             \
            g_hhist[(size_t)((s) * NCH + chain) * HID + ug] = hv;              \
        x0 = nx0; x1 = nx1; x2 = nx2;                                          \
    }

    for (int s = 0; s < S_STEPS; s += 2) {
        LSTM_STEP(s, 0);
        LSTM_STEP(s + 1, 1);
    }
#undef LSTM_STEP
}

// Deferred output projection: out[row] = b_lin + h_hist[row,:] . W_lin
__global__ void __launch_bounds__(256) out_kernel(
    const float* __restrict__ Wlin, const float* __restrict__ blin,
    float* __restrict__ out)
{
    const int lane = threadIdx.x & 31;
    const int warp = (blockIdx.x * blockDim.x + threadIdx.x) >> 5;
    const float w0 = Wlin[lane],      w1 = Wlin[lane + 32];
    const float w2 = Wlin[lane + 64], w3 = Wlin[lane + 96];
    const float bl = __ldg(blin);
    int row = warp * 8;
#pragma unroll
    for (int k = 0; k < 8; k++, row++) {
        if (row >= NROWS_TOTAL) return;
        const float* h = g_hhist + (size_t)row * HID;
        float s = h[lane] * w0 + h[lane + 32] * w1
                + h[lane + 64] * w2 + h[lane + 96] * w3;
#pragma unroll
        for (int off = 16; off; off >>= 1)
            s += __shfl_xor_sync(0xffffffffu, s, off);
        if (lane == 0) out[row] = s + bl;
    }
}

extern "C" void kernel_launch(void* const* d_in, const int* in_sizes, int n_in,
                              void* d_out, int out_size)
{
    const float* x     = (const float*)d_in[0];
    const float* W_ih  = (const float*)d_in[1];
    const float* W_hh  = (const float*)d_in[2];
    const float* b_ih  = (const float*)d_in[3];
    const float* b_hh  = (const float*)d_in[4];
    const float* W_lin = (const float*)d_in[5];
    const float* b_lin = (const float*)d_in[6];
    float* out = (float*)d_out;

    lstm_kernel<<<12 * CLS, 256>>>(x, W_ih, W_hh, b_ih, b_hh);
    out_kernel<<<3684, 256>>>(W_lin, b_lin, out);
}

// round 6
// speedup vs baseline: 1.2514x; 1.2514x over previous
#include <cuda_runtime.h>
#include <cstdint>

#define S_STEPS 19648   // B*N = 64*307 sequential LSTM steps
#define NCH 12          // T_IN: independent LSTM chains
#define HID 128
#define CLS 4           // CTAs per chain (cluster size) — verified optimum
#define NROWS_TOTAL (S_STEPS * NCH)

// h history for deferred output projection: 19648*12*128 floats = ~115 MB
__device__ float g_hhist[(size_t)S_STEPS * NCH * HID];

// ---------------- PTX helpers ----------------
__device__ __forceinline__ uint32_t smem_u32(const void* p) {
    uint32_t a;
    asm("{ .reg .u64 t; cvta.to.shared.u64 t, %1; cvt.u32.u64 %0, t; }"
        : "=r"(a) : "l"(p));
    return a;
}
__device__ __forceinline__ uint32_t my_cluster_rank() {
    uint32_t r; asm("mov.u32 %0, %%cluster_ctarank;" : "=r"(r)); return r;
}
__device__ __forceinline__ uint32_t mapa_u32(uint32_t laddr, uint32_t rk) {
    uint32_t r;
    asm("mapa.shared::cluster.u32 %0, %1, %2;" : "=r"(r) : "r"(laddr), "r"(rk));
    return r;
}
// 8-byte remote shared store with mbarrier transaction tracking.
__device__ __forceinline__ void st_async_b64(uint32_t raddr, unsigned long long v,
                                             uint32_t rmbar) {
    asm volatile(
        "st.async.shared::cluster.mbarrier::complete_tx::bytes.b64 [%0], %1, [%2];"
        :: "r"(raddr), "l"(v), "r"(rmbar) : "memory");
}
#define MBAR_INIT(a, n) \
    asm volatile("mbarrier.init.shared.b64 [%0], %1;" :: "r"(a), "r"((uint32_t)(n)) : "memory")
#define MBAR_EXPECT_TX(a, n) \
    asm volatile("mbarrier.arrive.expect_tx.shared.b64 _, [%0], %1;" :: "r"(a), "r"((uint32_t)(n)) : "memory")
#define MBAR_WAIT(a, par) do {                                              \
    asm volatile(                                                           \
        "{\n\t.reg .pred P1;\n\t"                                           \
        "WL_%=:\n\t"                                                        \
        "mbarrier.try_wait.parity.acquire.cta.shared::cta.b64 P1, [%0], %1, 0x989680;\n\t" \
        "@P1 bra.uni WD_%=;\n\t"                                            \
        "bra.uni WL_%=;\n\t"                                                \
        "WD_%=:\n\t}"                                                       \
        :: "r"(a), "r"((uint32_t)(par)) : "memory");                        \
} while (0)

__device__ __forceinline__ unsigned long long fma2(unsigned long long a,
                                                   unsigned long long b,
                                                   unsigned long long c) {
    unsigned long long d;
    asm("fma.rn.f32x2 %0, %1, %2, %3;" : "=l"(d) : "l"(a), "l"(b), "l"(c));
    return d;
}
__device__ __forceinline__ unsigned long long add2(unsigned long long a,
                                                   unsigned long long b) {
    unsigned long long d;
    asm("add.rn.f32x2 %0, %1, %2;" : "=l"(d) : "l"(a), "l"(b));
    return d;
}
__device__ __forceinline__ float unpack_sum(unsigned long long a) {
    uint32_t lo, hi;
    asm("mov.b64 {%0, %1}, %2;" : "=r"(lo), "=r"(hi) : "l"(a));
    return __uint_as_float(lo) + __uint_as_float(hi);
}
__device__ __forceinline__ unsigned long long pack2(float lo, float hi) {
    unsigned long long d;
    asm("mov.b64 %0, {%1, %2};" : "=l"(d) : "f"(lo), "f"(hi));
    return d;
}
__device__ __forceinline__ float tanh_fast(float x) {
    float y; asm("tanh.approx.f32 %0, %1;" : "=f"(y) : "f"(x)); return y;
}
__device__ __forceinline__ float sigmoid_fast(float x) {
    return fmaf(0.5f, tanh_fast(0.5f * x), 0.5f);
}
#define CLUSTER_SYNC() do { \
    asm volatile("barrier.cluster.arrive.aligned;" ::: "memory"); \
    asm volatile("barrier.cluster.wait.aligned;"   ::: "memory"); } while (0)

// ---------------- LSTM kernel ----------------
// 48 CTAs = 12 chains x 4-CTA clusters, 128 threads/CTA (1 warp per SMSP).
// CTA rank r owns hidden units [32r, 32r+32) = 128 gate rows; one FULL row
// (128 cols, 64 fma2, weights register-resident) per thread:
//   lane l: unit u8 = l&7 (warp w owns units 8w..8w+7), gate g = l>>3
//   row = g*128 + 32r + 8w + u8
// No cross-lane row reduction. Gate gather = 4 in-warp idx shuffles. Gates
// computed redundantly on all lanes (c replicated) so lanes 0..15 each publish
// ONE packed b64 (unit pair p=k>>2 of this warp -> rank k&3) via st.async.
// One mbarrier per step, 512B expect (64 msgs); no __syncthreads in the loop.
__global__ void __launch_bounds__(128, 1) __cluster_dims__(CLS, 1, 1)
lstm_kernel(const float* __restrict__ x,
            const float* __restrict__ W_ih,
            const float* __restrict__ W_hh,
            const float* __restrict__ b_ih,
            const float* __restrict__ b_hh)
{
    __shared__ __align__(16) float h_sh[2][HID];   // double-buffered hidden state
    __shared__ __align__(8)  unsigned long long mbar[2];

    const int tid  = threadIdx.x;
    const int w    = tid >> 5;
    const int l    = tid & 31;
    const uint32_t rank = my_cluster_rank();
    const int chain = blockIdx.x / CLS;

    const int u8  = l & 7;                  // unit within warp's 8
    const int g   = l >> 3;                 // gate 0..3 (i,f,g,o)
    const int ug  = 32 * (int)rank + 8 * w + u8;  // global hidden unit
    const int row = g * 128 + ug;           // row in W (4H x H)

    // Register-resident full W_hh row: 128 floats = 32 ull2 (128 regs)
    const ulonglong2* wrow =
        reinterpret_cast<const ulonglong2*>(W_hh + (size_t)row * HID);
    ulonglong2 wv[32];
#pragma unroll
    for (int j = 0; j < 32; j++) wv[j] = wrow[j];

    const float wx0 = W_ih[row * 3 + 0];
    const float wx1 = W_ih[row * 3 + 1];
    const float wx2 = W_ih[row * 3 + 2];
    const float bsum = b_ih[row] + b_hh[row];

    h_sh[0][tid] = 0.f;   // 128 threads cover all 128 h

    const uint32_t mb_l0 = smem_u32(&mbar[0]);
    const uint32_t mb_l1 = smem_u32(&mbar[1]);
    if (tid == 0) {
        MBAR_INIT(mb_l0, 1);
        MBAR_INIT(mb_l1, 1);
        MBAR_EXPECT_TX(mb_l1, 512);   // step 0 fills buffer 1 (64 x 8B msgs)
    }
    __syncthreads();   // local h_sh[0] zeros + mbar init done
    CLUSTER_SYNC();    // mbar init visible cluster-wide before any st.async

    // Per-lane send target (lanes 0..15): pair p = (l>>2)&3 of this warp's
    // units -> rank l&3. Buffer-1/mbar addresses by constant deltas.
    const int p_l = (l >> 2) & 3;
    const uint32_t la_pair =
        smem_u32(&h_sh[0][32 * (int)rank + 8 * w + 2 * p_l]);
    const uint32_t mybase  = mapa_u32(la_pair, (uint32_t)(l & 3));
    const uint32_t d_h1    = (uint32_t)(HID * sizeof(float));  // h_sh[1]-h_sh[0]
    const uint32_t d_mb0   = mb_l0 - la_pair;
    const uint32_t d_mb1   = mb_l1 - la_pair;

    float c = 0.f;        // cell state (replicated across all lanes)
    int ph0 = 0, ph1 = 0; // mbarrier phase parities

    // x layout: (B,N,F,T) -> element (s,f,t) at x[s*36 + f*12 + t]
    float x0 = x[chain], x1 = x[12 + chain], x2 = x[24 + chain];

#define LSTM_STEP(s, P)                                                        \
    {                                                                          \
        const int b = 1 - (P);                                                 \
        if (tid == 0 && (s) > 0 && (s) < S_STEPS - 1)                          \
            MBAR_EXPECT_TX((b) ? mb_l1 : mb_l0, 512);                          \
        /* prefetch next x (L2-resident, hidden under the wait) */             \
        float nx0 = 0.f, nx1 = 0.f, nx2 = 0.f;                                 \
        if ((s) + 1 < S_STEPS) {                                               \
            const float* xp = x + (size_t)((s) + 1) * 36 + chain;              \
            nx0 = __ldg(xp); nx1 = __ldg(xp + 12); nx2 = __ldg(xp + 24);       \
        }                                                                      \
        /* wait for all 128 h of step s (st.async from all 4 ranks) */         \
        if ((s) > 0) {                                                         \
            if (P) { MBAR_WAIT(mb_l1, ph1); ph1 ^= 1; }                        \
            else   { MBAR_WAIT(mb_l0, ph0); ph0 ^= 1; }                        \
        }                                                                      \
        /* full row: 64 fma2, 8 accumulator chains */                          \
        const ulonglong2* h4 = reinterpret_cast<const ulonglong2*>(h_sh[P]);   \
        unsigned long long a0 = 0ull, a1 = 0ull, a2 = 0ull, a3 = 0ull;         \
        unsigned long long a4 = 0ull, a5 = 0ull, a6 = 0ull, a7 = 0ull;         \
        _Pragma("unroll")                                                      \
        for (int j = 0; j < 32; j += 4) {                                      \
            ulonglong2 hA = h4[j];                                             \
            a0 = fma2(wv[j].x, hA.x, a0);                                      \
            a1 = fma2(wv[j].y, hA.y, a1);                                      \
            ulonglong2 hB = h4[j + 1];                                         \
            a2 = fma2(wv[j + 1].x, hB.x, a2);                                  \
            a3 = fma2(wv[j + 1].y, hB.y, a3);                                  \
            ulonglong2 hC = h4[j + 2];                                         \
            a4 = fma2(wv[j + 2].x, hC.x, a4);                                  \
            a5 = fma2(wv[j + 2].y, hC.y, a5);                                  \
            ulonglong2 hD = h4[j + 3];                                         \
            a6 = fma2(wv[j + 3].x, hD.x, a6);                                  \
            a7 = fma2(wv[j + 3].y, hD.y, a7);                                  \
        }                                                                      \
        unsigned long long t0 = add2(add2(a0, a1), add2(a2, a3));              \
        unsigned long long t1 = add2(add2(a4, a5), add2(a6, a7));              \
        float z = unpack_sum(add2(t0, t1))                                     \
                + bsum + wx0 * x0 + wx1 * x1 + wx2 * x2;                       \
        /* gather 4 gates of unit u8 (lanes u8 + 8g, all in this warp) */      \
        const unsigned fm = 0xffffffffu;                                       \
        float zi = __shfl_sync(fm, z, u8);                                     \
        float zf = __shfl_sync(fm, z, u8 + 8);                                 \
        float zg = __shfl_sync(fm, z, u8 + 16);                                \
        float zo = __shfl_sync(fm, z, u8 + 24);                                \
        /* gates on ALL lanes (warp-level MUFUs; c replicated per lane) */     \
        float si = sigmoid_fast(zi);                                           \
        float sf = sigmoid_fast(zf);                                           \
        float so = sigmoid_fast(zo);                                           \
        c = sf * c + si * tanh_fast(zg);                                       \
        float hv = so * tanh_fast(c);                                          \
        /* pack pair p_l: (h[2p], h[2p+1]) from lanes 2p, 2p+1 */              \
        float ha = __shfl_sync(fm, hv, 2 * p_l);                               \
        float hb = __shfl_sync(fm, hv, 2 * p_l + 1);                           \
        if ((s) + 1 < S_STEPS && l < 16)                                       \
            st_async_b64(mybase + ((b) ? d_h1 : 0u), pack2(ha, hb),            \
                         mybase + ((b) ? d_mb1 : d_mb0));                      \
        if (l < 8)                                                             \
            g_hhist[(size_t)((s) * NCH + chain) * HID + ug] = hv;              \
        x0 = nx0; x1 = nx1; x2 = nx2;                                          \
    }

    for (int s = 0; s < S_STEPS; s += 2) {
        LSTM_STEP(s, 0);
        LSTM_STEP(s + 1, 1);
    }
#undef LSTM_STEP
}

// Deferred output projection: out[row] = b_lin + h_hist[row,:] . W_lin
__global__ void __launch_bounds__(256) out_kernel(
    const float* __restrict__ Wlin, const float* __restrict__ blin,
    float* __restrict__ out)
{
    const int lane = threadIdx.x & 31;
    const int warp = (blockIdx.x * blockDim.x + threadIdx.x) >> 5;
    const float w0 = Wlin[lane],      w1 = Wlin[lane + 32];
    const float w2 = Wlin[lane + 64], w3 = Wlin[lane + 96];
    const float bl = __ldg(blin);
    int row = warp * 8;
#pragma unroll
    for (int k = 0; k < 8; k++, row++) {
        if (row >= NROWS_TOTAL) return;
        const float* h = g_hhist + (size_t)row * HID;
        float s = h[lane] * w0 + h[lane + 32] * w1
                + h[lane + 64] * w2 + h[lane + 96] * w3;
#pragma unroll
        for (int off = 16; off; off >>= 1)
            s += __shfl_xor_sync(0xffffffffu, s, off);
        if (lane == 0) out[row] = s + bl;
    }
}

extern "C" void kernel_launch(void* const* d_in, const int* in_sizes, int n_in,
                              void* d_out, int out_size)
{
    const float* x     = (const float*)d_in[0];
    const float* W_ih  = (const float*)d_in[1];
    const float* W_hh  = (const float*)d_in[2];
    const float* b_ih  = (const float*)d_in[3];
    const float* b_hh  = (const float*)d_in[4];
    const float* W_lin = (const float*)d_in[5];
    const float* b_lin = (const float*)d_in[6];
    float* out = (float*)d_out;

    lstm_kernel<<<12 * CLS, 128>>>(x, W_ih, W_hh, b_ih, b_hh);
    out_kernel<<<3684, 256>>>(W_lin, b_lin, out);
}

// round 7
// speedup vs baseline: 1.3678x; 1.0930x over previous
#include <cuda_runtime.h>
#include <cstdint>

#define S_STEPS 19648   // B*N = 64*307 sequential LSTM steps
#define NCH 12          // T_IN: independent LSTM chains
#define HID 128
#define CLS 4           // CTAs per chain (cluster size) — verified optimum
#define NROWS_TOTAL (S_STEPS * NCH)

// h history for deferred output projection: 19648*12*128 floats = ~115 MB
__device__ float g_hhist[(size_t)S_STEPS * NCH * HID];

// ---------------- PTX helpers ----------------
__device__ __forceinline__ uint32_t smem_u32(const void* p) {
    uint32_t a;
    asm("{ .reg .u64 t; cvta.to.shared.u64 t, %1; cvt.u32.u64 %0, t; }"
        : "=r"(a) : "l"(p));
    return a;
}
__device__ __forceinline__ uint32_t my_cluster_rank() {
    uint32_t r; asm("mov.u32 %0, %%cluster_ctarank;" : "=r"(r)); return r;
}
__device__ __forceinline__ uint32_t mapa_u32(uint32_t laddr, uint32_t rk) {
    uint32_t r;
    asm("mapa.shared::cluster.u32 %0, %1, %2;" : "=r"(r) : "r"(laddr), "r"(rk));
    return r;
}
// 8-byte remote shared store with mbarrier transaction tracking.
__device__ __forceinline__ void st_async_b64(uint32_t raddr, unsigned long long v,
                                             uint32_t rmbar) {
    asm volatile(
        "st.async.shared::cluster.mbarrier::complete_tx::bytes.b64 [%0], %1, [%2];"
        :: "r"(raddr), "l"(v), "r"(rmbar) : "memory");
}
#define MBAR_INIT(a, n) \
    asm volatile("mbarrier.init.shared.b64 [%0], %1;" :: "r"(a), "r"((uint32_t)(n)) : "memory")
#define MBAR_EXPECT_TX(a, n) \
    asm volatile("mbarrier.arrive.expect_tx.shared.b64 _, [%0], %1;" :: "r"(a), "r"((uint32_t)(n)) : "memory")
#define MBAR_WAIT(a, par) do {                                              \
    asm volatile(                                                           \
        "{\n\t.reg .pred P1;\n\t"                                           \
        "WL_%=:\n\t"                                                        \
        "mbarrier.try_wait.parity.acquire.cta.shared::cta.b64 P1, [%0], %1, 0x989680;\n\t" \
        "@P1 bra.uni WD_%=;\n\t"                                            \
        "bra.uni WL_%=;\n\t"                                                \
        "WD_%=:\n\t}"                                                       \
        :: "r"(a), "r"((uint32_t)(par)) : "memory");                        \
} while (0)

__device__ __forceinline__ unsigned long long fma2(unsigned long long a,
                                                   unsigned long long b,
                                                   unsigned long long c) {
    unsigned long long d;
    asm("fma.rn.f32x2 %0, %1, %2, %3;" : "=l"(d) : "l"(a), "l"(b), "l"(c));
    return d;
}
__device__ __forceinline__ unsigned long long add2(unsigned long long a,
                                                   unsigned long long b) {
    unsigned long long d;
    asm("add.rn.f32x2 %0, %1, %2;" : "=l"(d) : "l"(a), "l"(b));
    return d;
}
__device__ __forceinline__ float unpack_sum(unsigned long long a) {
    uint32_t lo, hi;
    asm("mov.b64 {%0, %1}, %2;" : "=r"(lo), "=r"(hi) : "l"(a));
    return __uint_as_float(lo) + __uint_as_float(hi);
}
__device__ __forceinline__ unsigned long long pack2(float lo, float hi) {
    unsigned long long d;
    asm("mov.b64 %0, {%1, %2};" : "=l"(d) : "f"(lo), "f"(hi));
    return d;
}
__device__ __forceinline__ float tanh_fast(float x) {
    float y; asm("tanh.approx.f32 %0, %1;" : "=f"(y) : "f"(x)); return y;
}
__device__ __forceinline__ float sigmoid_fast(float x) {
    return fmaf(0.5f, tanh_fast(0.5f * x), 0.5f);
}
#define CLUSTER_SYNC() do { \
    asm volatile("barrier.cluster.arrive.aligned;" ::: "memory"); \
    asm volatile("barrier.cluster.wait.aligned;"   ::: "memory"); } while (0)

// ---------------- LSTM kernel ----------------
// 48 CTAs = 12 chains x 4-CTA clusters, 128 threads/CTA (1 warp per SMSP).
// CTA rank r owns hidden units [32r, 32r+32); one FULL gate row per thread:
//   lane l: unit u8 = l&7 (warp w owns units 8w..8w+7), gate g = l>>3
//   row = g*128 + 32r + 8w + u8
// SPLIT MATVEC to hide the DSMEM flight: after gates,
//   (1) lanes 0..11 send the CTA's h pairs to the 3 remote ranks (st.async),
//   (2) own h written by plain STS + __syncthreads,
//   (3) partial dot over OWN 32 columns runs while remote h is in flight,
//   (4) mbarrier wait (expect 384B = 3 ranks x 32 x 4B), then remote 96 cols.
__global__ void __launch_bounds__(128, 1) __cluster_dims__(CLS, 1, 1)
lstm_kernel(const float* __restrict__ x,
            const float* __restrict__ W_ih,
            const float* __restrict__ W_hh,
            const float* __restrict__ b_ih,
            const float* __restrict__ b_hh)
{
    __shared__ __align__(16) float h_sh[2][HID];   // double-buffered hidden state
    __shared__ __align__(8)  unsigned long long mbar[2];

    const int tid  = threadIdx.x;
    const int w    = tid >> 5;
    const int l    = tid & 31;
    const int rank = (int)my_cluster_rank();
    const int chain = blockIdx.x / CLS;

    const int u8  = l & 7;                  // unit within warp's 8
    const int g   = l >> 3;                 // gate 0..3 (i,f,g,o)
    const int ug  = 32 * rank + 8 * w + u8; // global hidden unit
    const int row = g * 128 + ug;           // row in W (4H x H)

    // Register-resident W_hh row, split: own 32 cols (wl) / remote 96 (wr),
    // wr ordered by remote rank j=0..2 -> rk=(rank+1+j)&3, cols [32rk,32rk+32)
    const ulonglong2* wp =
        reinterpret_cast<const ulonglong2*>(W_hh + (size_t)row * HID);
    ulonglong2 wl[8], wr[24];
    int ob[3];  // byte offsets of remote column blocks within h row
#pragma unroll
    for (int k = 0; k < 8; k++) wl[k] = wp[rank * 8 + k];
#pragma unroll
    for (int j = 0; j < 3; j++) {
        const int rk = (rank + 1 + j) & 3;
        ob[j] = rk * 128;  // 32 floats * 4B
#pragma unroll
        for (int k = 0; k < 8; k++) wr[j * 8 + k] = wp[rk * 8 + k];
    }

    const float wx0 = W_ih[row * 3 + 0];
    const float wx1 = W_ih[row * 3 + 1];
    const float wx2 = W_ih[row * 3 + 2];
    const float bsum = b_ih[row] + b_hh[row];

    h_sh[0][tid] = 0.f;   // 128 threads cover all 128 h

    const uint32_t mb_l0 = smem_u32(&mbar[0]);
    const uint32_t mb_l1 = smem_u32(&mbar[1]);
    if (tid == 0) {
        MBAR_INIT(mb_l0, 1);
        MBAR_INIT(mb_l1, 1);
        MBAR_EXPECT_TX(mb_l1, 384);   // step-0 sends target buffer/mbar 1
    }
    __syncthreads();   // local h zeros + mbar init done
    CLUSTER_SYNC();    // mbar init visible cluster-wide before any st.async

    // Send targets (lanes 0..11): pair p=l&3 of this warp's units -> remote
    // rank j=l>>2 (dst = (rank+1+j)&3). Buffer-1/mbar addrs by const deltas.
    const int p_l = l & 3;
    const int dst = (rank + 1 + (l >> 2)) & 3;
    const uint32_t la_pair = smem_u32(&h_sh[0][32 * rank + 8 * w + 2 * p_l]);
    const uint32_t mybase  = mapa_u32(la_pair, (uint32_t)dst);
    const uint32_t d_h1    = (uint32_t)(HID * sizeof(float));
    const uint32_t d_mb0   = mb_l0 - la_pair;
    const uint32_t d_mb1   = mb_l1 - la_pair;

    float c = 0.f;        // cell state (replicated across lanes; valid for u8)
    int ph0 = 0, ph1 = 0; // mbarrier phase parities
    const unsigned fm = 0xffffffffu;

    // Step-0 pre-activation: h(-1)=0, so z = bsum + W_ih . x(0)
    float z = bsum + wx0 * x[chain] + wx1 * x[12 + chain] + wx2 * x[24 + chain];

#define LSTM_STEP(s, P)                                                        \
    {                                                                          \
        const int b = 1 - (P);                                                 \
        if (tid == 0 && (s) > 0 && (s) < S_STEPS - 1)                          \
            MBAR_EXPECT_TX((b) ? mb_l1 : mb_l0, 384);                          \
        /* prefetch x(s+1) (L2-resident) */                                    \
        float nx0 = 0.f, nx1 = 0.f, nx2 = 0.f;                                 \
        if ((s) + 1 < S_STEPS) {                                               \
            const float* xp = x + (size_t)((s) + 1) * 36 + chain;              \
            nx0 = __ldg(xp); nx1 = __ldg(xp + 12); nx2 = __ldg(xp + 24);       \
        }                                                                      \
        /* gates from carried z; computed on ALL lanes (c replicated) */       \
        float zi = __shfl_sync(fm, z, u8);                                     \
        float zf = __shfl_sync(fm, z, u8 + 8);                                 \
        float zg = __shfl_sync(fm, z, u8 + 16);                                \
        float zo = __shfl_sync(fm, z, u8 + 24);                                \
        float si = sigmoid_fast(zi);                                           \
        float sf = sigmoid_fast(zf);                                           \
        float so = sigmoid_fast(zo);                                           \
        c = sf * c + si * tanh_fast(zg);                                       \
        float hv = so * tanh_fast(c);                                          \
        /* fire remote sends ASAP: pair (h[2p], h[2p+1]) to rank dst */        \
        float ha = __shfl_sync(fm, hv, 2 * p_l);                               \
        float hb2 = __shfl_sync(fm, hv, 2 * p_l + 1);                          \
        if ((s) + 1 < S_STEPS && l < 12)                                       \
            st_async_b64(mybase + ((b) ? d_h1 : 0u), pack2(ha, hb2),           \
                         mybase + ((b) ? d_mb1 : d_mb0));                      \
        /* own h: plain local STS (no flight) + history store */               \
        if (l < 8) {                                                           \
            h_sh[b][ug] = hv;                                                  \
            g_hhist[(size_t)((s) * NCH + chain) * HID + ug] = hv;              \
        }                                                                      \
        __syncthreads();                                                       \
        if ((s) + 1 < S_STEPS) {                                               \
            /* own-column partial while remote h is in flight: 16 fma2 */      \
            const char* hb_ = (const char*)h_sh[b];                            \
            const ulonglong2* hl =                                             \
                reinterpret_cast<const ulonglong2*>(hb_ + rank * 128);         \
            unsigned long long a0 = 0ull, a1 = 0ull, a2 = 0ull, a3 = 0ull;     \
            unsigned long long a4 = 0ull, a5 = 0ull, a6 = 0ull, a7 = 0ull;     \
            _Pragma("unroll")                                                  \
            for (int k = 0; k < 8; k += 2) {                                   \
                ulonglong2 hA = hl[k];                                         \
                a0 = fma2(wl[k].x, hA.x, a0);                                  \
                a1 = fma2(wl[k].y, hA.y, a1);                                  \
                ulonglong2 hB = hl[k + 1];                                     \
                a2 = fma2(wl[k + 1].x, hB.x, a2);                              \
                a3 = fma2(wl[k + 1].y, hB.y, a3);                              \
            }                                                                  \
            /* wait for the 3 remote ranks' h (384B into mbar[b]) */           \
            if (b) { MBAR_WAIT(mb_l1, ph1); ph1 ^= 1; }                        \
            else   { MBAR_WAIT(mb_l0, ph0); ph0 ^= 1; }                        \
            /* remote 96 columns: 3 blocks x 16 fma2 */                        \
            _Pragma("unroll")                                                  \
            for (int j = 0; j < 3; j++) {                                      \
                const ulonglong2* hr =                                         \
                    reinterpret_cast<const ulonglong2*>(hb_ + ob[j]);          \
                _Pragma("unroll")                                              \
                for (int k = 0; k < 8; k += 2) {                               \
                    ulonglong2 hA = hr[k];                                     \
                    a4 = fma2(wr[j * 8 + k].x, hA.x, a4);                      \
                    a5 = fma2(wr[j * 8 + k].y, hA.y, a5);                      \
                    ulonglong2 hB = hr[k + 1];                                 \
                    a6 = fma2(wr[j * 8 + k + 1].x, hB.x, a6);                  \
                    a7 = fma2(wr[j * 8 + k + 1].y, hB.y, a7);                  \
                }                                                              \
            }                                                                  \
            unsigned long long t0 = add2(add2(a0, a1), add2(a2, a3));          \
            unsigned long long t1 = add2(add2(a4, a5), add2(a6, a7));          \
            z = unpack_sum(add2(t0, t1))                                       \
              + bsum + wx0 * nx0 + wx1 * nx1 + wx2 * nx2;                      \
        }                                                                      \
    }

    for (int s = 0; s < S_STEPS; s += 2) {
        LSTM_STEP(s, 0);
        LSTM_STEP(s + 1, 1);
    }
#undef LSTM_STEP
}

// Deferred output projection: out[row] = b_lin + h_hist[row,:] . W_lin
__global__ void __launch_bounds__(256) out_kernel(
    const float* __restrict__ Wlin, const float* __restrict__ blin,
    float* __restrict__ out)
{
    const int lane = threadIdx.x & 31;
    const int warp = (blockIdx.x * blockDim.x + threadIdx.x) >> 5;
    const float w0 = Wlin[lane],      w1 = Wlin[lane + 32];
    const float w2 = Wlin[lane + 64], w3 = Wlin[lane + 96];
    const float bl = __ldg(blin);
    int row = warp * 8;
#pragma unroll
    for (int k = 0; k < 8; k++, row++) {
        if (row >= NROWS_TOTAL) return;
        const float* h = g_hhist + (size_t)row * HID;
        float s = h[lane] * w0 + h[lane + 32] * w1
                + h[lane + 64] * w2 + h[lane + 96] * w3;
#pragma unroll
        for (int off = 16; off; off >>= 1)
            s += __shfl_xor_sync(0xffffffffu, s, off);
        if (lane == 0) out[row] = s + bl;
    }
}

extern "C" void kernel_launch(void* const* d_in, const int* in_sizes, int n_in,
                              void* d_out, int out_size)
{
    const float* x     = (const float*)d_in[0];
    const float* W_ih  = (const float*)d_in[1];
    const float* W_hh  = (const float*)d_in[2];
    const float* b_ih  = (const float*)d_in[3];
    const float* b_hh  = (const float*)d_in[4];
    const float* W_lin = (const float*)d_in[5];
    const float* b_lin = (const float*)d_in[6];
    float* out = (float*)d_out;

    lstm_kernel<<<12 * CLS, 128>>>(x, W_ih, W_hh, b_ih, b_hh);
    out_kernel<<<3684, 256>>>(W_lin, b_lin, out);
}